// round 9
// baseline (speedup 1.0000x reference)
#include <cuda_runtime.h>
#include <cuda_fp16.h>

#define BB 256   // batch
#define SS 256   // seq len / steps
#define DD 128   // decoder dim
#define GG 512   // 4*D gates
#define TN 512   // lookup-table intervals

// fp16x2 LSTM hidden weights, register-load layout for thread t=(gp,kq):
// reg j (0..31): gsel=j&1, kk=j>>1 -> gate g=2*gp+gsel, ks {kq*32+2kk, +1}
// flat uint idx = j*1024 + t. 128 KB total.
__device__ __align__(16) unsigned int g_Wpack[32768];
__device__ float g_w1sum[SS];
__device__ float g_bias[GG];

__device__ __forceinline__ float tanh_fast(float x) {
    float y;
    asm("tanh.approx.f32 %0, %1;" : "=f"(y) : "f"(x));
    return y;
}
__device__ __forceinline__ float sigmoid_fast(float x) {
    return fmaf(tanh_fast(0.5f * x), 0.5f, 0.5f);
}
__device__ __forceinline__ unsigned long long pack2(float a, float b) {
    unsigned long long r;
    asm("mov.b64 %0, {%1,%2};" : "=l"(r) : "f"(a), "f"(b));
    return r;
}

// ---------------------------------------------------------------------------
// Prep kernel: pack W_hh, row-sum W1_w, fuse biases. One-time.
// ---------------------------------------------------------------------------
__global__ void prep_kernel(const float* __restrict__ W1_w,
                            const float* __restrict__ W_hh,
                            const float* __restrict__ b_ih,
                            const float* __restrict__ b_hh) {
    int blk = blockIdx.x;
    int t = threadIdx.x;
    if (blk < 128) {
        int idx = blk * 256 + t;          // 0..32767
        int j  = idx >> 10;               // reg 0..31
        int tt = idx & 1023;              // owning thread
        int gp = tt & 255;
        int kq = tt >> 8;
        int g  = 2 * gp + (j & 1);
        int k0 = kq * 32 + 2 * (j >> 1);
        __half2 v = __halves2half2(__float2half_rn(W_hh[g * DD + k0]),
                                   __float2half_rn(W_hh[g * DD + k0 + 1]));
        g_Wpack[idx] = *(unsigned int*)&v;
    } else {
        int lane = t & 31, w = t >> 5;
        for (int r = 0; r < 32; r++) {
            int s = w * 32 + r;
            float acc = 0.f;
            #pragma unroll
            for (int i = 0; i < 8; i++) acc += W1_w[s * SS + lane + 32 * i];
            #pragma unroll
            for (int off = 16; off; off >>= 1)
                acc += __shfl_xor_sync(0xffffffffu, acc, off);
            if (lane == 0) g_w1sum[s] = acc;
        }
        g_bias[t]       = b_ih[t]       + b_hh[t];
        g_bias[t + 256] = b_ih[t + 256] + b_hh[t + 256];
    }
}

// ---------------------------------------------------------------------------
// Main kernel: 2 batch elements per CTA, 1024 threads, 256 LSTM steps.
// Attention collapsed to per-batch lerp tables (built once).
// LSTM dot: thread = (gate-pair, k-quarter); weights in 32 half2 registers;
// each h load feeds 4 FMAs (2 gates x 2 batches) -> half the LDS traffic.
// ---------------------------------------------------------------------------
__global__ __launch_bounds__(1024, 1)
void decoder_kernel(const float* __restrict__ enc,   // [B,S,E]
                    const float* __restrict__ W1_b,  // [S]
                    const float* __restrict__ W2_w,  // [S,2S]
                    const float* __restrict__ W2_b,  // [S]
                    const float* __restrict__ W_ih,  // [4D,E]
                    float* __restrict__ out)         // [S,B,D]
{
    // 16 KB pool: init/table-build buffers alias the steady-state gph array.
    __shared__ __align__(16) unsigned char pool[16384];
    float*  ebuf = (float*)pool;                          // [1024]      init
    float (*a_st)[256] = (float(*)[256])(pool + 4096);    // [2][256]    init
    float4 (*sAC)[128] = (float4(*)[128])(pool + 6144);   // [2][128]    build
    float4 (*sE)[128]  = (float4(*)[128])(pool + 10240);  // [2][128]    build
    float*  gph = (float*)pool;                           // [4][2][512] loop

    __shared__ __align__(16) float4 Ttab[2][TN];   // {g0x,g0y,dgx,dgy}
    __shared__ float2 tail2[2];
    __shared__ __align__(16) float h_s[2][DD];
    __shared__ __align__(16) float2 wred[2][4];
    __shared__ __align__(16) float2 wihs[GG];
    __shared__ float sbias[GG];

    const int bid = blockIdx.x;
    const int t = threadIdx.x;        // 0..1023
    const int lane = t & 31;
    const int warp = t >> 5;

    // ---- init loads ----
    ebuf[t] = enc[bid * 1024 + t];
    if (t < GG) { wihs[t] = ((const float2*)W_ih)[t]; sbias[t] = g_bias[t]; }
    if (t < 256) h_s[t >> 7][t & 127] = 0.f;
    __syncthreads();

    // a[m][s] = encflat[m] . W2_w[s,:] + W2_b[s] + W1_b[s]
    {
        const int m_w = warp >> 4;
        const float4* W2w4 = (const float4*)W2_w;
        const float4* e4   = (const float4*)(ebuf + m_w * 512);
        for (int r = 0; r < 16; r++) {
            int s = (warp & 15) * 16 + r;
            float acc = 0.f;
            #pragma unroll
            for (int i = 0; i < 4; i++) {
                float4 wv = W2w4[s * 128 + lane + 32 * i];
                float4 ev = e4[lane + 32 * i];
                acc += wv.x * ev.x + wv.y * ev.y + wv.z * ev.z + wv.w * ev.w;
            }
            #pragma unroll
            for (int off = 16; off; off >>= 1)
                acc += __shfl_xor_sync(0xffffffffu, acc, off);
            if (lane == 0) a_st[m_w][s] = acc + W2_b[s] + W1_b[s];
        }
    }
    __syncthreads();
    if (t < 256) {
        int m = t >> 7, p = t & 127;
        // NOTE: reads of a_st / ebuf precede any overwrite (sAC/sE are at
        // higher pool offsets; a_st[m][2p..] and ebuf[m*512+4p..] are only
        // read here, and sAC/sE regions don't overlap them).
        sAC[m][p] = make_float4(a_st[m][2 * p], a_st[m][2 * p + 1],
                                g_w1sum[2 * p], g_w1sum[2 * p + 1]);
        sE[m][p]  = make_float4(ebuf[m * 512 + 4 * p],     ebuf[m * 512 + 4 * p + 2],
                                ebuf[m * 512 + 4 * p + 1], ebuf[m * 512 + 4 * p + 3]);
    }
    __syncthreads();

    // Degree-5 Chebyshev-economized poly for exp(t), t in [-1,1], abs err <= 5e-5
    const unsigned long long P5 = pack2(0.00868688f, 0.00868688f);
    const unsigned long long P4 = pack2(0.04379392f, 0.04379392f);
    const unsigned long long P3 = pack2(0.16648880f, 0.16648880f);
    const unsigned long long P2 = pack2(0.49919676f, 0.49919676f);
    const unsigned long long P1 = pack2(1.00002231f, 1.00002231f);
    const unsigned long long P0 = pack2(1.00004478f, 1.00004478f);

    // ---- build lookup tables ----
    for (int idx = t; idx < 2 * (TN + 1); idx += 1024) {
        int m = (idx > TN) ? 1 : 0;
        int k = idx - m * (TN + 1);
        const double2* pAC = (const double2*)sAC[m];
        const double2* pE  = (const double2*)sE[m];
        float h = fmaf((float)k, 2.0f / TN, -1.0f);
        unsigned long long hd2;
        asm("mov.b64 %0, {%1,%1};" : "=l"(hd2) : "f"(h));
        unsigned long long Z2 = 0ull, n02 = 0ull, n12 = 0ull;
        #pragma unroll 4
        for (int i = 0; i < 128; i++) {
            double2 acd = pAC[i];
            double2 eed = pE[i];
            unsigned long long ap  = __double_as_longlong(acd.x);
            unsigned long long cp  = __double_as_longlong(acd.y);
            unsigned long long e0p = __double_as_longlong(eed.x);
            unsigned long long e1p = __double_as_longlong(eed.y);
            unsigned long long x2;
            asm("fma.rn.f32x2 %0, %1, %2, %3;" : "=l"(x2) : "l"(hd2), "l"(cp), "l"(ap));
            float x0, x1;
            asm("mov.b64 {%0,%1}, %2;" : "=f"(x0), "=f"(x1) : "l"(x2));
            float t0 = tanh_fast(x0);
            float t1 = tanh_fast(x1);
            unsigned long long t2;
            asm("mov.b64 %0, {%1,%2};" : "=l"(t2) : "f"(t0), "f"(t1));
            unsigned long long p;
            asm("fma.rn.f32x2 %0, %1, %2, %3;" : "=l"(p) : "l"(P5), "l"(t2), "l"(P4));
            asm("fma.rn.f32x2 %0, %0, %1, %2;" : "+l"(p) : "l"(t2), "l"(P3));
            asm("fma.rn.f32x2 %0, %0, %1, %2;" : "+l"(p) : "l"(t2), "l"(P2));
            asm("fma.rn.f32x2 %0, %0, %1, %2;" : "+l"(p) : "l"(t2), "l"(P1));
            asm("fma.rn.f32x2 %0, %0, %1, %2;" : "+l"(p) : "l"(t2), "l"(P0));
            asm("add.rn.f32x2 %0, %0, %1;"     : "+l"(Z2) : "l"(p));
            asm("fma.rn.f32x2 %0, %1, %2, %0;" : "+l"(n02) : "l"(p), "l"(e0p));
            asm("fma.rn.f32x2 %0, %1, %2, %0;" : "+l"(n12) : "l"(p), "l"(e1p));
        }
        float Zl, Zh, a0, a1, b0, b1;
        asm("mov.b64 {%0,%1}, %2;" : "=f"(Zl), "=f"(Zh) : "l"(Z2));
        asm("mov.b64 {%0,%1}, %2;" : "=f"(a0), "=f"(a1) : "l"(n02));
        asm("mov.b64 {%0,%1}, %2;" : "=f"(b0), "=f"(b1) : "l"(n12));
        float Z = Zl + Zh, n0 = a0 + a1, n1 = b0 + b1;
        float inv = __fdividef(1.f, Z);
        float gx = n0 * inv, gy = n1 * inv;
        if (k < TN) { Ttab[m][k].x = gx; Ttab[m][k].y = gy; }
        else        { tail2[m] = make_float2(gx, gy); }
    }
    __syncthreads();
    {   // slopes: exactly 1024 items = 1 per thread
        int m = t >> 9, k = t & (TN - 1);
        float2 cur = *(const float2*)&Ttab[m][k];
        float2 nxt = (k == TN - 1) ? tail2[m] : *(const float2*)&Ttab[m][k + 1];
        __syncthreads();
        Ttab[m][k].z = nxt.x - cur.x;
        Ttab[m][k].w = nxt.y - cur.y;
    }
    __syncthreads();

    // ---- roles + register weight load ----
    const int gp = t & 255;           // gate pair (gates 2gp, 2gp+1)
    const int kq = t >> 8;            // k-quarter 0..3 (warp-uniform)
    unsigned int Wr[32];
    {
        const unsigned int* wsrc = g_Wpack + t;
        #pragma unroll
        for (int j = 0; j < 32; j++) Wr[j] = wsrc[j * 1024];   // coalesced, one-time
    }
    float c_reg = 0.f;                // LSTM cell state for epilogue threads

    const float4* h40 = (const float4*)(h_s[0]) + (kq << 3);
    const float4* h41 = (const float4*)(h_s[1]) + (kq << 3);
    float2* gst = ((float2*)gph) + kq * 512 + gp;   // {gate0,gate1}; +256 for m=1

    for (int step = 0; step < SS; step++) {
        // ---- Phase 1a: h-dot (all threads; weights in registers) ----
        float a00 = 0.f, a01 = 0.f, a10 = 0.f, a11 = 0.f;
        #pragma unroll
        for (int jj = 0; jj < 8; jj++) {
            float4 hv0 = h40[jj];                   // LDS.128 broadcast
            float4 hv1 = h41[jj];                   // LDS.128 broadcast
            float2 w0a = __half22float2(*(const __half2*)&Wr[4 * jj + 0]); // g0 k{0,1}
            float2 w1a = __half22float2(*(const __half2*)&Wr[4 * jj + 1]); // g1 k{0,1}
            float2 w0b = __half22float2(*(const __half2*)&Wr[4 * jj + 2]); // g0 k{2,3}
            float2 w1b = __half22float2(*(const __half2*)&Wr[4 * jj + 3]); // g1 k{2,3}
            a00 = fmaf(hv0.x, w0a.x, a00);
            a10 = fmaf(hv0.x, w1a.x, a10);
            a01 = fmaf(hv1.x, w0a.x, a01);
            a11 = fmaf(hv1.x, w1a.x, a11);
            a00 = fmaf(hv0.y, w0a.y, a00);
            a10 = fmaf(hv0.y, w1a.y, a10);
            a01 = fmaf(hv1.y, w0a.y, a01);
            a11 = fmaf(hv1.y, w1a.y, a11);
            a00 = fmaf(hv0.z, w0b.x, a00);
            a10 = fmaf(hv0.z, w1b.x, a10);
            a01 = fmaf(hv1.z, w0b.x, a01);
            a11 = fmaf(hv1.z, w1b.x, a11);
            a00 = fmaf(hv0.w, w0b.y, a00);
            a10 = fmaf(hv0.w, w1b.y, a10);
            a01 = fmaf(hv1.w, w0b.y, a01);
            a11 = fmaf(hv1.w, w1b.y, a11);
        }
        gst[0]   = make_float2(a00, a10);   // m=0
        gst[256] = make_float2(a01, a11);   // m=1

        // ---- Phase 1b: attention lookup (threads 256..511, overlaps 1a) ----
        if (t >= 256 && t < 512) {
            int tt = t - 256;
            int m = tt >> 7, d2 = tt & 127;
            float h = h_s[m][d2];
            float uu = fmaf(h, (float)(TN / 2), (float)(TN / 2));
            int i = (int)uu;
            i = max(0, min(i, TN - 1));
            float f = uu - (float)i;
            float4 tv = Ttab[m][i];
            float gx = fmaf(f, tv.z, tv.x);
            float gy = fmaf(f, tv.w, tv.y);
            #pragma unroll
            for (int off = 16; off; off >>= 1) {
                gx += __shfl_xor_sync(0xffffffffu, gx, off);
                gy += __shfl_xor_sync(0xffffffffu, gy, off);
            }
            if (lane == 0) wred[m][(warp - 8) & 3] = make_float2(gx, gy);
        }
        __syncthreads();                         // B1

        // ---- Phase 2: ctx-combine + LSTM update (threads 0..255) ----
        if (t < 256) {
            int m = t >> 7, d = t & 127;
            float2 r0 = wred[m][0], r1 = wred[m][1], r2 = wred[m][2], r3 = wred[m][3];
            float x0c = (r0.x + r1.x + r2.x + r3.x) * (1.f / 128.f);
            float x1c = (r0.y + r1.y + r2.y + r3.y) * (1.f / 128.f);
            const float* gb = gph + m * 512;     // [kq*1024 + u]
            float gi = sbias[d];
            float gf = sbias[d + 128];
            float gg = sbias[d + 256];
            float go = sbias[d + 384];
            #pragma unroll
            for (int q = 0; q < 4; q++) {
                gi += gb[q * 1024 + d];
                gf += gb[q * 1024 + d + 128];
                gg += gb[q * 1024 + d + 256];
                go += gb[q * 1024 + d + 384];
            }
            float2 wi0 = wihs[d];
            float2 wi1 = wihs[d + 128];
            float2 wi2 = wihs[d + 256];
            float2 wi3 = wihs[d + 384];
            gi += x0c * wi0.x + x1c * wi0.y;
            gf += x0c * wi1.x + x1c * wi1.y;
            gg += x0c * wi2.x + x1c * wi2.y;
            go += x0c * wi3.x + x1c * wi3.y;
            float si = sigmoid_fast(gi);
            float sf = sigmoid_fast(gf);
            float so = sigmoid_fast(go);
            c_reg = fmaf(sf, c_reg, si * tanh_fast(gg));
            float h = so * tanh_fast(c_reg);
            h_s[m][d] = h;
            out[(size_t)step * (BB * DD) + (2 * bid + m) * DD + d] = h;
        }
        __syncthreads();                         // B2
    }
}

// ---------------------------------------------------------------------------
extern "C" void kernel_launch(void* const* d_in, const int* in_sizes, int n_in,
                              void* d_out, int out_size) {
    const float* enc  = (const float*)d_in[0];
    const float* W1_w = (const float*)d_in[1];
    const float* W1_b = (const float*)d_in[2];
    const float* W2_w = (const float*)d_in[3];
    const float* W2_b = (const float*)d_in[4];
    const float* W_ih = (const float*)d_in[5];
    const float* W_hh = (const float*)d_in[6];
    const float* b_ih = (const float*)d_in[7];
    const float* b_hh = (const float*)d_in[8];
    float* out = (float*)d_out;

    prep_kernel<<<129, 256>>>(W1_w, W_hh, b_ih, b_hh);
    decoder_kernel<<<BB / 2, 1024>>>(enc, W1_b, W2_w, W2_b, W_ih, out);
}

// round 11
// speedup vs baseline: 1.2241x; 1.2241x over previous
#include <cuda_runtime.h>
#include <cuda_fp16.h>

#define BB 256   // batch
#define SS 256   // seq len / steps
#define DD 128   // decoder dim
#define GG 512   // 4*D gates
#define TN 512   // lookup-table intervals

// fp16x2 LSTM hidden weights: g_Wpack[j*512 + u] = half2{W_hh[u][2j], W_hh[u][2j+1]},
// j = 0..63, u = gate 0..511. 128 KB; loaded into registers once per CTA.
__device__ __align__(16) unsigned int g_Wpack[32768];
__device__ float g_w1sum[SS];
__device__ float g_bias[GG];

__device__ __forceinline__ float tanh_fast(float x) {
    float y;
    asm("tanh.approx.f32 %0, %1;" : "=f"(y) : "f"(x));
    return y;
}
__device__ __forceinline__ float sigmoid_fast(float x) {
    return fmaf(tanh_fast(0.5f * x), 0.5f, 0.5f);
}
__device__ __forceinline__ unsigned long long pack2(float a, float b) {
    unsigned long long r;
    asm("mov.b64 %0, {%1,%2};" : "=l"(r) : "f"(a), "f"(b));
    return r;
}

// ---------------------------------------------------------------------------
// Prep kernel: pack W_hh, row-sum W1_w, fuse biases. One-time.
// ---------------------------------------------------------------------------
__global__ void prep_kernel(const float* __restrict__ W1_w,
                            const float* __restrict__ W_hh,
                            const float* __restrict__ b_ih,
                            const float* __restrict__ b_hh) {
    int blk = blockIdx.x;
    int t = threadIdx.x;
    if (blk < 128) {
        int idx = blk * 256 + t;          // 0..32767
        int j = idx >> 9;                 // k-pair 0..63
        int u = idx & 511;                // gate
        __half2 v = __halves2half2(__float2half_rn(W_hh[u * DD + 2 * j]),
                                   __float2half_rn(W_hh[u * DD + 2 * j + 1]));
        g_Wpack[idx] = *(unsigned int*)&v;
    } else {
        int lane = t & 31, w = t >> 5;
        for (int r = 0; r < 32; r++) {
            int s = w * 32 + r;
            float acc = 0.f;
            #pragma unroll
            for (int i = 0; i < 8; i++) acc += W1_w[s * SS + lane + 32 * i];
            #pragma unroll
            for (int off = 16; off; off >>= 1)
                acc += __shfl_xor_sync(0xffffffffu, acc, off);
            if (lane == 0) g_w1sum[s] = acc;
        }
        g_bias[t]       = b_ih[t]       + b_hh[t];
        g_bias[t + 256] = b_ih[t + 256] + b_hh[t + 256];
    }
}

// ---------------------------------------------------------------------------
// Main kernel: 2 batch elements per CTA, 512 threads (128-reg budget, no
// spills), 256 LSTM steps. Thread u owns gate u: all 128 W_hh[u][*] weights
// in 64 half2 registers; computes both batches with packed f32x2 FMA.
// Attention collapsed to per-batch lerp tables (built once).
// ---------------------------------------------------------------------------
__global__ __launch_bounds__(512, 1)
void decoder_kernel(const float* __restrict__ enc,   // [B,S,E]
                    const float* __restrict__ W1_b,  // [S]
                    const float* __restrict__ W2_w,  // [S,2S]
                    const float* __restrict__ W2_b,  // [S]
                    const float* __restrict__ W_ih,  // [4D,E]
                    float* __restrict__ out)         // [S,B,D]
{
    __shared__ __align__(16) float4 sAC[2][128];
    __shared__ __align__(16) float4 sE[2][128];
    __shared__ __align__(16) float  ebuf[1024];
    __shared__ float a_st[2][256];
    __shared__ __align__(16) float4 Ttab[2][TN];   // {g0x,g0y,dgx,dgy}
    __shared__ float2 tail2[2];
    __shared__ __align__(16) float gates_s[2][GG];
    __shared__ __align__(16) float h_s[2][DD];
    __shared__ __align__(16) float2 wred[2][4];
    __shared__ __align__(16) float2 wihs[GG];
    __shared__ float sbias[GG];

    const int bid = blockIdx.x;
    const int t = threadIdx.x;        // 0..511
    const int lane = t & 31;
    const int warp = t >> 5;

    // ---- init loads ----
    ebuf[t]       = enc[bid * 1024 + t];
    ebuf[t + 512] = enc[bid * 1024 + t + 512];
    wihs[t]  = ((const float2*)W_ih)[t];
    sbias[t] = g_bias[t];
    if (t < 256) h_s[t >> 7][t & 127] = 0.f;
    __syncthreads();

    // a[m][s] = encflat[m] . W2_w[s,:] + W2_b[s] + W1_b[s]; 16 warps x 32 rows
    {
        const int m_w = warp >> 3;                  // warps 0-7: m=0, 8-15: m=1
        const float4* W2w4 = (const float4*)W2_w;
        const float4* e4   = (const float4*)(ebuf + m_w * 512);
        for (int r = 0; r < 32; r++) {
            int s = (warp & 7) * 32 + r;
            float acc = 0.f;
            #pragma unroll
            for (int i = 0; i < 4; i++) {
                float4 wv = W2w4[s * 128 + lane + 32 * i];
                float4 ev = e4[lane + 32 * i];
                acc += wv.x * ev.x + wv.y * ev.y + wv.z * ev.z + wv.w * ev.w;
            }
            #pragma unroll
            for (int off = 16; off; off >>= 1)
                acc += __shfl_xor_sync(0xffffffffu, acc, off);
            if (lane == 0) a_st[m_w][s] = acc + W2_b[s] + W1_b[s];
        }
    }
    __syncthreads();
    if (t < 256) {
        int m = t >> 7, p = t & 127;
        sAC[m][p] = make_float4(a_st[m][2 * p], a_st[m][2 * p + 1],
                                g_w1sum[2 * p], g_w1sum[2 * p + 1]);
        sE[m][p]  = make_float4(ebuf[m * 512 + 4 * p],     ebuf[m * 512 + 4 * p + 2],
                                ebuf[m * 512 + 4 * p + 1], ebuf[m * 512 + 4 * p + 3]);
    }
    __syncthreads();

    // Degree-5 Chebyshev-economized poly for exp(t), t in [-1,1], abs err <= 5e-5
    const unsigned long long P5 = pack2(0.00868688f, 0.00868688f);
    const unsigned long long P4 = pack2(0.04379392f, 0.04379392f);
    const unsigned long long P3 = pack2(0.16648880f, 0.16648880f);
    const unsigned long long P2 = pack2(0.49919676f, 0.49919676f);
    const unsigned long long P1 = pack2(1.00002231f, 1.00002231f);
    const unsigned long long P0 = pack2(1.00004478f, 1.00004478f);

    // ---- build lookup tables ----
    for (int idx = t; idx < 2 * (TN + 1); idx += 512) {
        int m = (idx > TN) ? 1 : 0;
        int k = idx - m * (TN + 1);
        const double2* pAC = (const double2*)sAC[m];
        const double2* pE  = (const double2*)sE[m];
        float h = fmaf((float)k, 2.0f / TN, -1.0f);
        unsigned long long hd2;
        asm("mov.b64 %0, {%1,%1};" : "=l"(hd2) : "f"(h));
        unsigned long long Z2 = 0ull, n02 = 0ull, n12 = 0ull;
        #pragma unroll 4
        for (int i = 0; i < 128; i++) {
            double2 acd = pAC[i];
            double2 eed = pE[i];
            unsigned long long ap  = __double_as_longlong(acd.x);
            unsigned long long cp  = __double_as_longlong(acd.y);
            unsigned long long e0p = __double_as_longlong(eed.x);
            unsigned long long e1p = __double_as_longlong(eed.y);
            unsigned long long x2;
            asm("fma.rn.f32x2 %0, %1, %2, %3;" : "=l"(x2) : "l"(hd2), "l"(cp), "l"(ap));
            float x0, x1;
            asm("mov.b64 {%0,%1}, %2;" : "=f"(x0), "=f"(x1) : "l"(x2));
            float t0 = tanh_fast(x0);
            float t1 = tanh_fast(x1);
            unsigned long long t2;
            asm("mov.b64 %0, {%1,%2};" : "=l"(t2) : "f"(t0), "f"(t1));
            unsigned long long p;
            asm("fma.rn.f32x2 %0, %1, %2, %3;" : "=l"(p) : "l"(P5), "l"(t2), "l"(P4));
            asm("fma.rn.f32x2 %0, %0, %1, %2;" : "+l"(p) : "l"(t2), "l"(P3));
            asm("fma.rn.f32x2 %0, %0, %1, %2;" : "+l"(p) : "l"(t2), "l"(P2));
            asm("fma.rn.f32x2 %0, %0, %1, %2;" : "+l"(p) : "l"(t2), "l"(P1));
            asm("fma.rn.f32x2 %0, %0, %1, %2;" : "+l"(p) : "l"(t2), "l"(P0));
            asm("add.rn.f32x2 %0, %0, %1;"     : "+l"(Z2) : "l"(p));
            asm("fma.rn.f32x2 %0, %1, %2, %0;" : "+l"(n02) : "l"(p), "l"(e0p));
            asm("fma.rn.f32x2 %0, %1, %2, %0;" : "+l"(n12) : "l"(p), "l"(e1p));
        }
        float Zl, Zh, a0, a1, b0, b1;
        asm("mov.b64 {%0,%1}, %2;" : "=f"(Zl), "=f"(Zh) : "l"(Z2));
        asm("mov.b64 {%0,%1}, %2;" : "=f"(a0), "=f"(a1) : "l"(n02));
        asm("mov.b64 {%0,%1}, %2;" : "=f"(b0), "=f"(b1) : "l"(n12));
        float Z = Zl + Zh, n0 = a0 + a1, n1 = b0 + b1;
        float inv = __fdividef(1.f, Z);
        float gx = n0 * inv, gy = n1 * inv;
        if (k < TN) { Ttab[m][k].x = gx; Ttab[m][k].y = gy; }
        else        { tail2[m] = make_float2(gx, gy); }
    }
    __syncthreads();
    {   // slopes: 1024 items, 2 per thread
        #pragma unroll
        for (int it = 0; it < 2; it++) {
            int idx = t + it * 512;
            int m = idx >> 9, k = idx & (TN - 1);
            float2 cur = *(const float2*)&Ttab[m][k];
            float2 nxt = (k == TN - 1) ? tail2[m] : *(const float2*)&Ttab[m][k + 1];
            __syncthreads();
            Ttab[m][k].z = nxt.x - cur.x;
            Ttab[m][k].w = nxt.y - cur.y;
            __syncthreads();
        }
    }

    // ---- register weight load: 64 half2 = all 128 k for gate t ----
    unsigned int Wr[64];
    {
        const unsigned int* wsrc = g_Wpack + t;
        #pragma unroll
        for (int j = 0; j < 64; j++) Wr[j] = wsrc[j * 512];   // coalesced, one-time
    }
    const unsigned long long bias2 = pack2(sbias[t], 0.f);
    float c_reg = 0.f;                // cell state for epilogue threads (0..255)

    const double2* H0 = (const double2*)h_s[0];
    const double2* H1 = (const double2*)h_s[1];

    for (int step = 0; step < SS; step++) {
        // ---- Phase 1a: full gate dot for both batches (f32x2 FMA) ----
        // FIX vs R10: BOTH accumulators start from bias2 (batch 1 previously
        // ran with no bias at all -> rel_err 0.705).
        unsigned long long A0 = bias2, A1 = bias2;
        #pragma unroll 8
        for (int j = 0; j < 32; j++) {
            double2 hp0 = H0[j];                    // LDS.128 broadcast: {h4j..h4j+3}
            double2 hp1 = H1[j];
            float2 wa = __half22float2(*(const __half2*)&Wr[2 * j]);
            float2 wb = __half22float2(*(const __half2*)&Wr[2 * j + 1]);
            unsigned long long WA = pack2(wa.x, wa.y);
            unsigned long long WB = pack2(wb.x, wb.y);
            asm("fma.rn.f32x2 %0, %1, %2, %0;" : "+l"(A0)
                : "l"(__double_as_longlong(hp0.x)), "l"(WA));
            asm("fma.rn.f32x2 %0, %1, %2, %0;" : "+l"(A1)
                : "l"(__double_as_longlong(hp1.x)), "l"(WA));
            asm("fma.rn.f32x2 %0, %1, %2, %0;" : "+l"(A0)
                : "l"(__double_as_longlong(hp0.y)), "l"(WB));
            asm("fma.rn.f32x2 %0, %1, %2, %0;" : "+l"(A1)
                : "l"(__double_as_longlong(hp1.y)), "l"(WB));
        }
        {
            float g0l, g0h, g1l, g1h;
            asm("mov.b64 {%0,%1}, %2;" : "=f"(g0l), "=f"(g0h) : "l"(A0));
            asm("mov.b64 {%0,%1}, %2;" : "=f"(g1l), "=f"(g1h) : "l"(A1));
            gates_s[0][t] = g0l + g0h;
            gates_s[1][t] = g1l + g1h;
        }

        // ---- Phase 1b: attention lookup (warps 8..15: one (m,d) each) ----
        if (t >= 256) {
            int tt = t - 256;
            int m = tt >> 7, d2 = tt & 127;
            float h = h_s[m][d2];
            float uu = fmaf(h, (float)(TN / 2), (float)(TN / 2));
            int i = (int)uu;
            i = max(0, min(i, TN - 1));
            float f = uu - (float)i;
            float4 tv = Ttab[m][i];
            float gx = fmaf(f, tv.z, tv.x);
            float gy = fmaf(f, tv.w, tv.y);
            #pragma unroll
            for (int off = 16; off; off >>= 1) {
                gx += __shfl_xor_sync(0xffffffffu, gx, off);
                gy += __shfl_xor_sync(0xffffffffu, gy, off);
            }
            if (lane == 0) wred[m][(warp - 8) & 3] = make_float2(gx, gy);
        }
        __syncthreads();                         // B1

        // ---- Phase 2: ctx-combine + LSTM update (threads 0..255) ----
        if (t < 256) {
            int m = t >> 7, d = t & 127;
            float2 r0 = wred[m][0], r1 = wred[m][1], r2 = wred[m][2], r3 = wred[m][3];
            float x0c = (r0.x + r1.x + r2.x + r3.x) * (1.f / 128.f);
            float x1c = (r0.y + r1.y + r2.y + r3.y) * (1.f / 128.f);
            float2 wi0 = wihs[d];
            float2 wi1 = wihs[d + 128];
            float2 wi2 = wihs[d + 256];
            float2 wi3 = wihs[d + 384];
            float gi = gates_s[m][d]       + x0c * wi0.x + x1c * wi0.y;
            float gf = gates_s[m][d + 128] + x0c * wi1.x + x1c * wi1.y;
            float gg = gates_s[m][d + 256] + x0c * wi2.x + x1c * wi2.y;
            float go = gates_s[m][d + 384] + x0c * wi3.x + x1c * wi3.y;
            float si = sigmoid_fast(gi);
            float sf = sigmoid_fast(gf);
            float so = sigmoid_fast(go);
            c_reg = fmaf(sf, c_reg, si * tanh_fast(gg));
            float h = so * tanh_fast(c_reg);
            h_s[m][d] = h;
            out[(size_t)step * (BB * DD) + (2 * bid + m) * DD + d] = h;
        }
        __syncthreads();                         // B2
    }
}

// ---------------------------------------------------------------------------
extern "C" void kernel_launch(void* const* d_in, const int* in_sizes, int n_in,
                              void* d_out, int out_size) {
    const float* enc  = (const float*)d_in[0];
    const float* W1_w = (const float*)d_in[1];
    const float* W1_b = (const float*)d_in[2];
    const float* W2_w = (const float*)d_in[3];
    const float* W2_b = (const float*)d_in[4];
    const float* W_ih = (const float*)d_in[5];
    const float* W_hh = (const float*)d_in[6];
    const float* b_ih = (const float*)d_in[7];
    const float* b_hh = (const float*)d_in[8];
    float* out = (float*)d_out;

    prep_kernel<<<129, 256>>>(W1_w, W_hh, b_ih, b_hh);
    decoder_kernel<<<BB / 2, 512>>>(enc, W1_b, W2_w, W2_b, W_ih, out);
}